// round 1
// baseline (speedup 1.0000x reference)
#include <cuda_runtime.h>
#include <math.h>

// Problem constants
#define BB 32
#define CC 64
#define VV 1024
#define TT 24
#define COUT 64
#define MROWS (BB*CC)          // 2048
#define PART ((size_t)MROWS*VV) // 2,097,152 floats per (B*C, V) plane
#define CVSZ (CC*VV)            // 65536

// Scratch (static device memory; allocation-free at runtime)
__device__ __align__(128) float g_xT[(size_t)TT*MROWS*VV];   // [t][b*C+c][v]  192MB
__device__ __align__(128) float g_ys[(size_t)TT*MROWS*VV];   // hy per step; ys[t] is h for t+1
__device__ __align__(128) float g_G[3*(size_t)MROWS*VV];     // [comb | x1 | x2]
__device__ __align__(128) float g_gates[(size_t)BB*4*CC*VV]; // [b][4C][v]
__device__ __align__(128) float g_c[(size_t)MROWS*VV];       // cell state

// ---------------------------------------------------------------------------
// Transpose x: (B,C,V,T) -> xT (T, B*C, V). Coalesced in and out via smem tile.
__global__ void transpose_x(const float* __restrict__ x) {
    __shared__ float tile[32][25];               // [v][t], padded
    int r  = blockIdx.x;                         // b*C+c
    int v0 = blockIdx.y * 32;
    const float* src = x + ((size_t)r * VV + v0) * TT; // 32*24 contiguous floats
    for (int i = threadIdx.x; i < 32 * TT; i += blockDim.x) {
        int v = i / TT, t = i % TT;
        tile[v][t] = src[i];
    }
    __syncthreads();
    for (int i = threadIdx.x; i < 32 * TT; i += blockDim.x) {
        int t = i / 32, v = i % 32;
        g_xT[(size_t)t * PART + (size_t)r * VV + v0 + v] = tile[v][t];
    }
}

__global__ void zero_c() {
    size_t i = (size_t)blockIdx.x * blockDim.x + threadIdx.x;
    g_c[i] = 0.0f;
}

// comb = x_t + h_{t-1}   (h_{-1} = 0)
__global__ void add_comb(int t) {
    size_t i = ((size_t)blockIdx.x * blockDim.x + threadIdx.x);
    float4 xv = *reinterpret_cast<const float4*>(&g_xT[(size_t)t * PART + i * 4]);
    float4 hv = make_float4(0.f, 0.f, 0.f, 0.f);
    if (t > 0) hv = *reinterpret_cast<const float4*>(&g_ys[(size_t)(t - 1) * PART + i * 4]);
    float4 o = make_float4(xv.x + hv.x, xv.y + hv.y, xv.z + hv.z, xv.w + hv.w);
    *reinterpret_cast<float4*>(&g_G[i * 4]) = o;
}

// ---------------------------------------------------------------------------
// Hop SGEMM: C(2048x1024) = A(2048x1024, src part of g_G) * B(1024x1024, support)
// 128x128x8 tiles, 8x8 microtile, register-prefetch double buffer.
__global__ __launch_bounds__(256) void sgemm_hop(const float* __restrict__ Bmat, int src_part) {
    const int BK = 8;
    __shared__ float As[BK][128];
    __shared__ float Bs[BK][128];
    const float* Aop = g_G + (size_t)src_part * PART;
    float*       Cop = g_G + (size_t)(src_part + 1) * PART;

    int tid = threadIdx.x;
    int bx = blockIdx.x, by = blockIdx.y;
    const float* Aptr = Aop + (size_t)by * 128 * 1024;
    const float* Bptr = Bmat + bx * 128;
    float*       Cptr = Cop + (size_t)by * 128 * 1024 + bx * 128;

    int aRow = tid >> 1,  aCol = (tid & 1) * 4;   // 128 rows x 2 float4
    int bRow = tid >> 5,  bCol = (tid & 31) * 4;  // 8 rows x 32 float4
    int tRow = (tid >> 4) * 8, tCol = (tid & 15) * 8;

    float acc[8][8];
    #pragma unroll
    for (int i = 0; i < 8; i++)
        #pragma unroll
        for (int j = 0; j < 8; j++) acc[i][j] = 0.f;

    float4 a4 = *reinterpret_cast<const float4*>(Aptr + (size_t)aRow * 1024 + aCol);
    float4 b4 = *reinterpret_cast<const float4*>(Bptr + (size_t)bRow * 1024 + bCol);

    for (int k0 = 0; k0 < 1024; k0 += BK) {
        As[aCol + 0][aRow] = a4.x;
        As[aCol + 1][aRow] = a4.y;
        As[aCol + 2][aRow] = a4.z;
        As[aCol + 3][aRow] = a4.w;
        *reinterpret_cast<float4*>(&Bs[bRow][bCol]) = b4;
        __syncthreads();
        if (k0 + BK < 1024) {
            a4 = *reinterpret_cast<const float4*>(Aptr + (size_t)aRow * 1024 + (k0 + BK) + aCol);
            b4 = *reinterpret_cast<const float4*>(Bptr + (size_t)(k0 + BK + bRow) * 1024 + bCol);
        }
        #pragma unroll
        for (int k = 0; k < BK; k++) {
            float regM[8], regN[8];
            #pragma unroll
            for (int i = 0; i < 8; i++) regM[i] = As[k][tRow + i];
            #pragma unroll
            for (int j = 0; j < 8; j++) regN[j] = Bs[k][tCol + j];
            #pragma unroll
            for (int i = 0; i < 8; i++)
                #pragma unroll
                for (int j = 0; j < 8; j++) acc[i][j] += regM[i] * regN[j];
        }
        __syncthreads();
    }
    #pragma unroll
    for (int i = 0; i < 8; i++)
        #pragma unroll
        for (int j = 0; j < 8; j += 4) {
            float4 o = make_float4(acc[i][j], acc[i][j+1], acc[i][j+2], acc[i][j+3]);
            *reinterpret_cast<float4*>(Cptr + (size_t)(tRow + i) * 1024 + tCol + j) = o;
        }
}

// ---------------------------------------------------------------------------
// Gate GEMM per batch b: gates[b](256x1024) = W_gout(256x192) @ Gb(192x1024) + bias
// Gb rows gathered from the 3 concat parts of g_G.
__global__ __launch_bounds__(256) void gate_gemm(const float* __restrict__ W,
                                                 const float* __restrict__ bias) {
    const int BK = 8;
    __shared__ float As[BK][128];
    __shared__ float Bs[BK][128];
    int tid = threadIdx.x;
    int bx = blockIdx.x, by = blockIdx.y, b = blockIdx.z;

    int aRow = tid >> 1,  aCol = (tid & 1) * 4;
    int bRow = tid >> 5,  bCol = (tid & 31) * 4;
    int tRow = (tid >> 4) * 8, tCol = (tid & 15) * 8;

    const float* Wp = W + (size_t)(by * 128) * 192;

    float acc[8][8];
    #pragma unroll
    for (int i = 0; i < 8; i++)
        #pragma unroll
        for (int j = 0; j < 8; j++) acc[i][j] = 0.f;

    auto rowptr = [&](int k) -> const float* {
        return g_G + (size_t)(k >> 6) * PART + (size_t)b * CVSZ +
               (size_t)(k & 63) * VV + bx * 128;
    };

    float4 a4 = *reinterpret_cast<const float4*>(Wp + (size_t)aRow * 192 + aCol);
    float4 b4 = *reinterpret_cast<const float4*>(rowptr(bRow) + bCol);

    for (int k0 = 0; k0 < 192; k0 += BK) {
        As[aCol + 0][aRow] = a4.x;
        As[aCol + 1][aRow] = a4.y;
        As[aCol + 2][aRow] = a4.z;
        As[aCol + 3][aRow] = a4.w;
        *reinterpret_cast<float4*>(&Bs[bRow][bCol]) = b4;
        __syncthreads();
        if (k0 + BK < 192) {
            a4 = *reinterpret_cast<const float4*>(Wp + (size_t)aRow * 192 + (k0 + BK) + aCol);
            b4 = *reinterpret_cast<const float4*>(rowptr(k0 + BK + bRow) + bCol);
        }
        #pragma unroll
        for (int k = 0; k < BK; k++) {
            float regM[8], regN[8];
            #pragma unroll
            for (int i = 0; i < 8; i++) regM[i] = As[k][tRow + i];
            #pragma unroll
            for (int j = 0; j < 8; j++) regN[j] = Bs[k][tCol + j];
            #pragma unroll
            for (int i = 0; i < 8; i++)
                #pragma unroll
                for (int j = 0; j < 8; j++) acc[i][j] += regM[i] * regN[j];
        }
        __syncthreads();
    }

    float* outp = g_gates + (size_t)b * (4 * CVSZ) + (size_t)(by * 128) * VV + bx * 128;
    #pragma unroll
    for (int i = 0; i < 8; i++) {
        float bv = bias[by * 128 + tRow + i];
        #pragma unroll
        for (int j = 0; j < 8; j += 4) {
            float4 o = make_float4(acc[i][j] + bv, acc[i][j+1] + bv,
                                   acc[i][j+2] + bv, acc[i][j+3] + bv);
            *reinterpret_cast<float4*>(outp + (size_t)(tRow + i) * 1024 + tCol + j) = o;
        }
    }
}

// ---------------------------------------------------------------------------
// LSTM pointwise: cy = sig(f)*c + sig(i)*g ; hy = sig(o)*tanh(cy) -> ys[t]
__global__ void lstm_step(int t) {
    size_t n = (size_t)blockIdx.x * blockDim.x + threadIdx.x;  // [0, 2048*1024)
    int b = (int)(n >> 16);
    int rem = (int)(n & 65535);
    size_t gi = (size_t)b * (4 * CVSZ) + rem;
    float ig = g_gates[gi];
    float fg = g_gates[gi + CVSZ];
    float gg = g_gates[gi + 2 * CVSZ];
    float og = g_gates[gi + 3 * CVSZ];
    float si = 1.f / (1.f + expf(-ig));
    float sf = 1.f / (1.f + expf(-fg));
    float so = 1.f / (1.f + expf(-og));
    float cy = sf * g_c[n] + si * gg;
    g_c[n] = cy;
    g_ys[(size_t)t * PART + n] = so * tanhf(cy);
}

// ---------------------------------------------------------------------------
// Final projection: out[b,o,v,t] = sum_c Wout[o,c]*ys[t,b,c,v] + bout[o]
// Block = (v-tile of 8, b). smem-stage ys so each thread owns a full t-row
// (contiguous 96B output writes).
__global__ __launch_bounds__(256) void proj_out(const float* __restrict__ Wout,
                                                const float* __restrict__ bout,
                                                float* __restrict__ out) {
    __shared__ float sm[TT * CC * 8];   // 48KB: [t][c][vv]
    int b  = blockIdx.y;
    int v0 = blockIdx.x * 8;
    for (int i = threadIdx.x; i < TT * CC * 8; i += 256) {
        int t = i / (CC * 8);
        int rem = i % (CC * 8);
        int c = rem >> 3, vv = rem & 7;
        sm[i] = g_ys[(size_t)t * PART + (size_t)b * CVSZ + (size_t)c * VV + v0 + vv];
    }
    __syncthreads();
    for (int p = threadIdx.x; p < COUT * 8; p += 256) {
        int o = p >> 3, vv = p & 7;
        float acc[TT];
        #pragma unroll
        for (int t = 0; t < TT; t++) acc[t] = 0.f;
        for (int c = 0; c < CC; c++) {
            float w = Wout[o * CC + c];
            #pragma unroll
            for (int t = 0; t < TT; t++) acc[t] += w * sm[t * (CC * 8) + c * 8 + vv];
        }
        float bo = bout[o];
        float* op = out + ((size_t)(b * COUT + o) * VV + v0 + vv) * TT;
        #pragma unroll
        for (int t = 0; t < TT; t++) op[t] = acc[t] + bo;
    }
}

// ---------------------------------------------------------------------------
extern "C" void kernel_launch(void* const* d_in, const int* in_sizes, int n_in,
                              void* d_out, int out_size) {
    const float* x      = (const float*)d_in[0];
    const float* Amat   = (const float*)d_in[1];
    const float* W_gout = (const float*)d_in[2];
    const float* b_gout = (const float*)d_in[3];
    const float* W_out  = (const float*)d_in[4];
    const float* b_out  = (const float*)d_in[5];
    float* out = (float*)d_out;

    transpose_x<<<dim3(MROWS, VV / 32), 256>>>(x);
    zero_c<<<(MROWS * VV) / 256, 256>>>();

    dim3 hopGrid(VV / 128, MROWS / 128);       // (8, 16)
    dim3 gateGrid(VV / 128, 256 / 128, BB);    // (8, 2, 32)

    for (int t = 0; t < TT; t++) {
        add_comb<<<(MROWS * VV / 4) / 256, 256>>>(t);
        sgemm_hop<<<hopGrid, 256>>>(Amat, 0);  // x1 = comb @ A
        sgemm_hop<<<hopGrid, 256>>>(Amat, 1);  // x2 = x1 @ A
        gate_gemm<<<gateGrid, 256>>>(W_gout, b_gout);
        lstm_step<<<(MROWS * VV) / 256, 256>>>(t);
    }

    proj_out<<<dim3(VV / 8, BB), 256>>>(W_out, b_out, out);
}